// round 7
// baseline (speedup 1.0000x reference)
#include <cuda_runtime.h>
#include <cuda_bf16.h>
#include <cstdint>

// out = ReLU(LayerNorm(emb[:, :, :256] @ W_enc + b_enc) * gamma + beta)
// (reference kNN/gather path is a provable no-op: pooled == embeddings)
//
// R7: bf16x3 mma.sync, restructured for 2 CTAs/SM:
//   BM=32, 256 threads (8 warps x warp-tile 32x64), 96KB smem/CTA,
//   2-stage cp.async B ring. Co-resident CTAs hide each other's stalls.

#define KDIM    256
#define NDIM    512
#define DROW    512
#define BM      32
#define THREADS 256
#define NSTAGE  16          // K / 16
#define LN_EPS  1e-5f

typedef uint32_t u32;

// prepped W: [n][k] bf16, hi and lo parts (256 KB each, L2-resident)
__device__ __nv_bfloat16 g_Whi[NDIM * KDIM];
__device__ __nv_bfloat16 g_Wlo[NDIM * KDIM];

// ---- smem layout (bytes) ----
// A_hi [32][256] bf16 swizzled : 0     .. 16383
// A_lo                         : 16384 .. 32767
// B ring: 2 stages x 32KB      : 32768 .. 98303   (stage: 512 n x 64B)
// epilogue reuses [0..66559] as h[32][520] f32
#define SM_ALO  16384
#define SM_B    32768
#define SMEM_TOTAL (32768 + 2 * 32768)   // 98304
#define HSTRIDE 520

__device__ __forceinline__ u32 smem_u32(const void* p) {
    u32 a;
    asm("{ .reg .u64 t; cvta.to.shared.u64 t, %1; cvt.u32.u64 %0, t; }" : "=r"(a) : "l"(p));
    return a;
}
__device__ __forceinline__ void cp16(u32 dst, const void* src) {
    asm volatile("cp.async.cg.shared.global [%0], [%1], 16;" :: "r"(dst), "l"(src));
}
__device__ __forceinline__ void cp_commit() { asm volatile("cp.async.commit_group;"); }
__device__ __forceinline__ void cp_wait0() { asm volatile("cp.async.wait_group 0;"); }

__device__ __forceinline__ void ldsm4(u32* r, u32 addr) {
    asm volatile("ldmatrix.sync.aligned.m8n8.x4.shared.b16 {%0,%1,%2,%3}, [%4];"
                 : "=r"(r[0]), "=r"(r[1]), "=r"(r[2]), "=r"(r[3]) : "r"(addr));
}
__device__ __forceinline__ void mma16816(float* d, const u32* a, const u32* b) {
    asm volatile(
        "mma.sync.aligned.m16n8k16.row.col.f32.bf16.bf16.f32 "
        "{%0,%1,%2,%3}, {%4,%5,%6,%7}, {%8,%9}, {%0,%1,%2,%3};"
        : "+f"(d[0]), "+f"(d[1]), "+f"(d[2]), "+f"(d[3])
        : "r"(a[0]), "r"(a[1]), "r"(a[2]), "r"(a[3]), "r"(b[0]), "r"(b[1]));
}

// ---------------- prep: W [k][n] f32 -> Whi/Wlo [n][k] bf16 ----------------
__global__ void prep_w(const float* __restrict__ W) {
    const int idx = blockIdx.x * blockDim.x + threadIdx.x;   // 0..32767
    const int n  = idx & 511;
    const int k4 = idx >> 9;                                  // 0..63
    unsigned short h[4], l[4];
    #pragma unroll
    for (int e = 0; e < 4; e++) {
        const float w = W[(size_t)(k4 * 4 + e) * NDIM + n];   // coalesced over n
        const __nv_bfloat16 hi = __float2bfloat16(w);
        const __nv_bfloat16 lo = __float2bfloat16(w - __bfloat162float(hi));
        h[e] = __bfloat16_as_ushort(hi);
        l[e] = __bfloat16_as_ushort(lo);
    }
    uint2 hp = make_uint2((u32)h[0] | ((u32)h[1] << 16), (u32)h[2] | ((u32)h[3] << 16));
    uint2 lp = make_uint2((u32)l[0] | ((u32)l[1] << 16), (u32)l[2] | ((u32)l[3] << 16));
    *(uint2*)&g_Whi[(size_t)n * KDIM + k4 * 4] = hp;
    *(uint2*)&g_Wlo[(size_t)n * KDIM + k4 * 4] = lp;
}

// ---------------- main fused GEMM + LN + ReLU ----------------
__global__ __launch_bounds__(THREADS, 2)
void gemm_ln_mma(const float* __restrict__ emb,
                 const float* __restrict__ bias,
                 const float* __restrict__ gamma,
                 const float* __restrict__ beta,
                 float* __restrict__ out) {
    extern __shared__ char smem[];
    const u32 sb   = smem_u32(smem);
    const int tid  = threadIdx.x;
    const int lane = tid & 31;
    const int w    = tid >> 5;       // 8 warps; warp w owns cols w*64..w*64+63
    const int m0   = blockIdx.x * BM;

    // ---- B stage loader: 2048 x 16B chunks, 8 per thread ----
    auto cpB = [&](int s) {
        const u32 bbase = sb + SM_B + (s & 1) * 32768;
        #pragma unroll
        for (int j = 0; j < 8; j++) {
            const int i  = tid + THREADS * j;
            const int n  = i >> 2;
            const int cb = i & 3;
            const char* src = (const char*)(cb < 2 ? g_Whi : g_Wlo)
                            + (size_t)n * 512 + s * 32 + (cb & 1) * 16;
            cp16(bbase + n * 64 + (((u32)cb ^ ((n >> 1) & 3)) << 4), src);
        }
    };

    cpB(0); cp_commit();

    // ---- A: load 32x256 f32, split to bf16 hi/lo into swizzled smem ----
    #pragma unroll
    for (int i = 0; i < 8; i++) {
        const int f   = tid + THREADS * i;    // float4 index, 2048 total
        const int row = f >> 6;
        const int q   = f & 63;               // float4 within row (k = 4q)
        const float4 v = *(const float4*)&emb[(size_t)(m0 + row) * DROW + q * 4];
        unsigned short h[4], l[4];
        const float vv[4] = {v.x, v.y, v.z, v.w};
        #pragma unroll
        for (int e = 0; e < 4; e++) {
            const __nv_bfloat16 hi = __float2bfloat16(vv[e]);
            const __nv_bfloat16 lo = __float2bfloat16(vv[e] - __bfloat162float(hi));
            h[e] = __bfloat16_as_ushort(hi);
            l[e] = __bfloat16_as_ushort(lo);
        }
        const u32 addr = sb + row * 512 + ((((u32)(q >> 1)) ^ (row & 7)) << 4) + (q & 1) * 8;
        asm volatile("st.shared.v2.b32 [%0], {%1, %2};" :: "r"(addr),
                     "r"((u32)h[0] | ((u32)h[1] << 16)), "r"((u32)h[2] | ((u32)h[3] << 16)));
        asm volatile("st.shared.v2.b32 [%0], {%1, %2};" :: "r"(addr + SM_ALO),
                     "r"((u32)l[0] | ((u32)l[1] << 16)), "r"((u32)l[2] | ((u32)l[3] << 16)));
    }

    // ---- per-lane ldmatrix geometry ----
    const int a_row0  = ((lane >> 3) & 1) * 8 + (lane & 7);   // rows 0..15 (+16 for mt=1)
    const int a_khalf = lane >> 4;
    u32 offB[4];
    #pragma unroll
    for (int p = 0; p < 4; p++) {
        const int n  = w * 64 + p * 16 + ((lane >> 4) & 1) * 8 + (lane & 7);
        const int cb = (lane >> 3) & 1;
        offB[p] = n * 64 + (((u32)cb ^ ((n >> 1) & 3)) << 4);
    }

    float d[2][8][4];
    #pragma unroll
    for (int mt = 0; mt < 2; mt++)
        #pragma unroll
        for (int j = 0; j < 8; j++)
            #pragma unroll
            for (int e = 0; e < 4; e++) d[mt][j][e] = 0.0f;

    // ---- mainloop over 16 k-stages (2-stage ring, prefetch distance 1) ----
    #pragma unroll 1
    for (int s = 0; s < NSTAGE; s++) {
        cp_wait0();
        __syncthreads();        // B[s] visible; all warps done reading buffer (s+1)&1
        if (s + 1 < NSTAGE) { cpB(s + 1); cp_commit(); }

        u32 ah[2][4], al[2][4];
        #pragma unroll
        for (int mt = 0; mt < 2; mt++) {
            const int row = a_row0 + mt * 16;
            const u32 ad = sb + row * 512 + ((((u32)(2 * s + a_khalf)) ^ (row & 7)) << 4);
            ldsm4(ah[mt], ad);
            ldsm4(al[mt], ad + SM_ALO);
        }
        const u32 bbase = sb + SM_B + (s & 1) * 32768;
        #pragma unroll
        for (int p = 0; p < 4; p++) {
            u32 bh[4], bl[4];
            ldsm4(bh, bbase + offB[p]);
            ldsm4(bl, (bbase + offB[p]) ^ 32);   // lo chunks = hi chunks ^ 32B
            #pragma unroll
            for (int mt = 0; mt < 2; mt++)
                #pragma unroll
                for (int e = 0; e < 2; e++) {
                    float* dd = d[mt][p * 2 + e];
                    mma16816(dd, ah[mt], &bh[2 * e]);   // hi*hi
                    mma16816(dd, ah[mt], &bl[2 * e]);   // hi*lo
                    mma16816(dd, al[mt], &bh[2 * e]);   // lo*hi
                }
        }
    }

    // ---- epilogue: acc -> smem h[32][520], then warp-row LN + ReLU ----
    __syncthreads();
    float* hb = (float*)smem;
    #pragma unroll
    for (int mt = 0; mt < 2; mt++)
        #pragma unroll
        for (int j = 0; j < 8; j++) {
            const int row = mt * 16 + (lane >> 2);
            const int col = w * 64 + j * 8 + (lane & 3) * 2;
            *(float2*)&hb[row * HSTRIDE + col]       = make_float2(d[mt][j][0], d[mt][j][1]);
            *(float2*)&hb[(row + 8) * HSTRIDE + col] = make_float2(d[mt][j][2], d[mt][j][3]);
        }
    __syncthreads();

    float bz[16], gm[16], bt[16];
    #pragma unroll
    for (int j = 0; j < 4; j++) {
        const int col = lane * 4 + 128 * j;
        *(float4*)&bz[j * 4] = *(const float4*)&bias[col];
        *(float4*)&gm[j * 4] = *(const float4*)&gamma[col];
        *(float4*)&bt[j * 4] = *(const float4*)&beta[col];
    }

    #pragma unroll
    for (int r = 0; r < 4; r++) {
        const int row = w * 4 + r;            // 8 warps x 4 rows = 32
        float h[16];
        float s = 0.f, sq = 0.f;
        #pragma unroll
        for (int j = 0; j < 4; j++) {
            float4 v = *(const float4*)&hb[row * HSTRIDE + lane * 4 + 128 * j];
            h[j * 4 + 0] = v.x + bz[j * 4 + 0];
            h[j * 4 + 1] = v.y + bz[j * 4 + 1];
            h[j * 4 + 2] = v.z + bz[j * 4 + 2];
            h[j * 4 + 3] = v.w + bz[j * 4 + 3];
        }
        #pragma unroll
        for (int i = 0; i < 16; i++) { s += h[i]; sq += h[i] * h[i]; }
        #pragma unroll
        for (int o = 16; o > 0; o >>= 1) {
            s  += __shfl_xor_sync(0xFFFFFFFFu, s,  o);
            sq += __shfl_xor_sync(0xFFFFFFFFu, sq, o);
        }
        const float mu   = s * (1.0f / NDIM);
        const float var  = sq * (1.0f / NDIM) - mu * mu;
        const float rstd = rsqrtf(var + LN_EPS);
        float y[16];
        #pragma unroll
        for (int i = 0; i < 16; i++)
            y[i] = fmaxf((h[i] - mu) * rstd * gm[i] + bt[i], 0.0f);
        const size_t orow = (size_t)(m0 + row) * NDIM;
        #pragma unroll
        for (int j = 0; j < 4; j++)
            *(float4*)&out[orow + lane * 4 + 128 * j] = *(float4*)&y[j * 4];
    }
}

extern "C" void kernel_launch(void* const* d_in, const int* in_sizes, int n_in,
                              void* d_out, int out_size) {
    const float* emb   = (const float*)d_in[0];
    const float* W_enc = (const float*)d_in[3];
    const float* b_enc = (const float*)d_in[4];
    const float* gamma = (const float*)d_in[5];
    const float* beta  = (const float*)d_in[6];
    float* out = (float*)d_out;

    cudaFuncSetAttribute(gemm_ln_mma,
                         cudaFuncAttributeMaxDynamicSharedMemorySize, SMEM_TOTAL);

    prep_w<<<128, 256>>>(W_enc);

    const int M = in_sizes[0] / DROW;       // 16384
    gemm_ln_mma<<<M / BM, THREADS, SMEM_TOTAL>>>(emb, b_enc, gamma, beta, out);
}

// round 8
// speedup vs baseline: 2.0912x; 2.0912x over previous
#include <cuda_runtime.h>
#include <cuda_fp16.h>
#include <cstdint>

// out = ReLU(LayerNorm(emb[:, :, :256] @ W_enc + b_enc) * gamma + beta)
// (reference kNN/gather path is a provable no-op: pooled == embeddings)
//
// R8: single-term fp16 mma.sync (f32 accumulate). Predicted rel_err ~3e-4
// (dropped-residual model calibrated on R6's bf16x3 = 4.47e-6 measurement).
// BM=64, 512 thr / 16 warps (warp tile 32x64), 8 k32-stages, 3-deep cp.async ring.

#define KDIM    256
#define NDIM    512
#define DROW    512
#define BM      64
#define THREADS 512
#define NSTAGE  8           // K / 32
#define LN_EPS  1e-5f

typedef uint32_t u32;

// prepped W: [n][k] fp16 (256 KB, L2-resident)
__device__ __half g_Wh[NDIM * KDIM];

// ---- smem layout (bytes) ----
// A [64][256] fp16 swizzled (row stride 512B) : 0     .. 32767
// B ring: 3 stages x 32KB (512 n x 64B)       : 32768 .. 131071
// epilogue reuses [0..133119] as h[64][520] f32
#define SM_B    32768
#define SMEM_TOTAL 133120
#define HSTRIDE 520

__device__ __forceinline__ u32 smem_u32(const void* p) {
    u32 a;
    asm("{ .reg .u64 t; cvta.to.shared.u64 t, %1; cvt.u32.u64 %0, t; }" : "=r"(a) : "l"(p));
    return a;
}
__device__ __forceinline__ void cp16(u32 dst, const void* src) {
    asm volatile("cp.async.cg.shared.global [%0], [%1], 16;" :: "r"(dst), "l"(src));
}
__device__ __forceinline__ void cp_commit() { asm volatile("cp.async.commit_group;"); }
template <int N>
__device__ __forceinline__ void cp_wait() { asm volatile("cp.async.wait_group %0;" :: "n"(N)); }

__device__ __forceinline__ void ldsm4(u32* r, u32 addr) {
    asm volatile("ldmatrix.sync.aligned.m8n8.x4.shared.b16 {%0,%1,%2,%3}, [%4];"
                 : "=r"(r[0]), "=r"(r[1]), "=r"(r[2]), "=r"(r[3]) : "r"(addr));
}
__device__ __forceinline__ void mma16816(float* d, const u32* a, const u32* b) {
    asm volatile(
        "mma.sync.aligned.m16n8k16.row.col.f32.f16.f16.f32 "
        "{%0,%1,%2,%3}, {%4,%5,%6,%7}, {%8,%9}, {%0,%1,%2,%3};"
        : "+f"(d[0]), "+f"(d[1]), "+f"(d[2]), "+f"(d[3])
        : "r"(a[0]), "r"(a[1]), "r"(a[2]), "r"(a[3]), "r"(b[0]), "r"(b[1]));
}

// ---------------- prep: W [k][n] f32 -> g_Wh [n][k] fp16 ----------------
__global__ void prep_w(const float* __restrict__ W) {
    const int idx = blockIdx.x * blockDim.x + threadIdx.x;   // 0..32767
    const int n  = idx & 511;
    const int k4 = idx >> 9;                                  // 0..63
    unsigned short h[4];
    #pragma unroll
    for (int e = 0; e < 4; e++) {
        const float w = W[(size_t)(k4 * 4 + e) * NDIM + n];   // coalesced over n
        h[e] = __half_as_ushort(__float2half_rn(w));
    }
    *(uint2*)&g_Wh[(size_t)n * KDIM + k4 * 4] =
        make_uint2((u32)h[0] | ((u32)h[1] << 16), (u32)h[2] | ((u32)h[3] << 16));
}

// ---------------- main fused GEMM + LN + ReLU ----------------
__global__ __launch_bounds__(THREADS, 1)
void gemm_ln_mma(const float* __restrict__ emb,
                 const float* __restrict__ bias,
                 const float* __restrict__ gamma,
                 const float* __restrict__ beta,
                 float* __restrict__ out) {
    extern __shared__ char smem[];
    const u32 sb   = smem_u32(smem);
    const int tid  = threadIdx.x;
    const int lane = tid & 31;
    const int w    = tid >> 5;       // 16 warps
    const int wr   = w >> 3;         // 0..1 : row block of 32
    const int wc   = w & 7;          // 0..7 : col block of 64
    const int m0   = blockIdx.x * BM;

    // ---- B stage loader: 2048 x 16B chunks (512 n x 4 k-quarters), 4/thread ----
    auto cpB = [&](int s) {
        const u32 bbase = sb + SM_B + (s % 3) * 32768;
        #pragma unroll
        for (int j = 0; j < 4; j++) {
            const int i  = tid + THREADS * j;
            const int n  = i >> 2;
            const int cb = i & 3;    // 16B chunk = 8 k-values within the k32 stage
            cp16(bbase + n * 64 + (((u32)cb ^ ((n >> 1) & 3)) << 4),
                 (const char*)g_Wh + (size_t)n * 512 + s * 64 + cb * 16);
        }
    };

    cpB(0); cp_commit();
    cpB(1); cp_commit();

    // ---- A: load 64x256 f32, convert to fp16 into swizzled smem ----
    // row stride 512B = 32 x 16B chunks; phys chunk = c ^ (row & 7)
    #pragma unroll
    for (int i = 0; i < 8; i++) {
        const int f   = tid + THREADS * i;    // float4 index, 4096 total
        const int row = f >> 6;
        const int q   = f & 63;               // float4 within row (k = 4q)
        const float4 v = *(const float4*)&emb[(size_t)(m0 + row) * DROW + q * 4];
        const unsigned short h0 = __half_as_ushort(__float2half_rn(v.x));
        const unsigned short h1 = __half_as_ushort(__float2half_rn(v.y));
        const unsigned short h2 = __half_as_ushort(__float2half_rn(v.z));
        const unsigned short h3 = __half_as_ushort(__float2half_rn(v.w));
        const u32 addr = sb + row * 512 + ((((u32)(q >> 1)) ^ (row & 7)) << 4) + (q & 1) * 8;
        asm volatile("st.shared.v2.b32 [%0], {%1, %2};" :: "r"(addr),
                     "r"((u32)h0 | ((u32)h1 << 16)), "r"((u32)h2 | ((u32)h3 << 16)));
    }

    // ---- per-lane ldmatrix geometry ----
    const int a_row0  = wr * 32 + ((lane >> 3) & 1) * 8 + (lane & 7);
    const int a_khalf = lane >> 4;
    u32 offB[4];
    #pragma unroll
    for (int p = 0; p < 4; p++) {
        const int n  = wc * 64 + p * 16 + ((lane >> 4) & 1) * 8 + (lane & 7);
        const int cb = (lane >> 3) & 1;
        offB[p] = n * 64 + (((u32)cb ^ ((n >> 1) & 3)) << 4);
    }

    float d[2][8][4];
    #pragma unroll
    for (int mt = 0; mt < 2; mt++)
        #pragma unroll
        for (int j = 0; j < 8; j++)
            #pragma unroll
            for (int e = 0; e < 4; e++) d[mt][j][e] = 0.0f;

    // ---- mainloop: 8 k32-stages, 3-deep ring, prefetch distance 2 ----
    #pragma unroll 1
    for (int s = 0; s < NSTAGE; s++) {
        if (s < NSTAGE - 1) cp_wait<1>();   // group s complete (s+1 may fly)
        else                cp_wait<0>();
        __syncthreads();                    // B[s] visible; ring slot (s+2)%3 free
        if (s + 2 < NSTAGE) { cpB(s + 2); cp_commit(); }

        // A fragments: chunks 4s+khalf and 4s+2+khalf (== ^2 -> addr ^ 32)
        u32 ah[2][2][4];
        #pragma unroll
        for (int mt = 0; mt < 2; mt++) {
            const int row = a_row0 + mt * 16;
            const u32 ad = sb + row * 512 + ((((u32)(4 * s + a_khalf)) ^ (row & 7)) << 4);
            ldsm4(ah[mt][0], ad);
            ldsm4(ah[mt][1], ad ^ 32);
        }
        const u32 bbase = sb + SM_B + (s % 3) * 32768;
        #pragma unroll
        for (int p = 0; p < 4; p++) {
            u32 b0[4], b1[4];
            ldsm4(b0, bbase + offB[p]);          // k 0..15 of stage
            ldsm4(b1, (bbase + offB[p]) ^ 32);   // k 16..31 (cb ^ 2)
            #pragma unroll
            for (int mt = 0; mt < 2; mt++)
                #pragma unroll
                for (int e = 0; e < 2; e++) {
                    float* dd = d[mt][p * 2 + e];
                    mma16816(dd, ah[mt][0], &b0[2 * e]);
                    mma16816(dd, ah[mt][1], &b1[2 * e]);
                }
        }
    }

    // ---- epilogue: acc -> smem h[64][520], then warp-row LN + ReLU ----
    __syncthreads();
    float* hb = (float*)smem;
    #pragma unroll
    for (int mt = 0; mt < 2; mt++)
        #pragma unroll
        for (int j = 0; j < 8; j++) {
            const int row = wr * 32 + mt * 16 + (lane >> 2);
            const int col = wc * 64 + j * 8 + (lane & 3) * 2;
            *(float2*)&hb[row * HSTRIDE + col]       = make_float2(d[mt][j][0], d[mt][j][1]);
            *(float2*)&hb[(row + 8) * HSTRIDE + col] = make_float2(d[mt][j][2], d[mt][j][3]);
        }
    __syncthreads();

    float bz[16], gm[16], bt[16];
    #pragma unroll
    for (int j = 0; j < 4; j++) {
        const int col = lane * 4 + 128 * j;
        *(float4*)&bz[j * 4] = *(const float4*)&bias[col];
        *(float4*)&gm[j * 4] = *(const float4*)&gamma[col];
        *(float4*)&bt[j * 4] = *(const float4*)&beta[col];
    }

    #pragma unroll
    for (int r = 0; r < 4; r++) {
        const int row = w * 4 + r;            // 16 warps x 4 rows = 64
        float h[16];
        float s = 0.f, sq = 0.f;
        #pragma unroll
        for (int j = 0; j < 4; j++) {
            float4 v = *(const float4*)&hb[row * HSTRIDE + lane * 4 + 128 * j];
            h[j * 4 + 0] = v.x + bz[j * 4 + 0];
            h[j * 4 + 1] = v.y + bz[j * 4 + 1];
            h[j * 4 + 2] = v.z + bz[j * 4 + 2];
            h[j * 4 + 3] = v.w + bz[j * 4 + 3];
        }
        #pragma unroll
        for (int i = 0; i < 16; i++) { s += h[i]; sq += h[i] * h[i]; }
        #pragma unroll
        for (int o = 16; o > 0; o >>= 1) {
            s  += __shfl_xor_sync(0xFFFFFFFFu, s,  o);
            sq += __shfl_xor_sync(0xFFFFFFFFu, sq, o);
        }
        const float mu   = s * (1.0f / NDIM);
        const float var  = sq * (1.0f / NDIM) - mu * mu;
        const float rstd = rsqrtf(var + LN_EPS);
        float y[16];
        #pragma unroll
        for (int i = 0; i < 16; i++)
            y[i] = fmaxf((h[i] - mu) * rstd * gm[i] + bt[i], 0.0f);
        const size_t orow = (size_t)(m0 + row) * NDIM;
        #pragma unroll
        for (int j = 0; j < 4; j++)
            *(float4*)&out[orow + lane * 4 + 128 * j] = *(float4*)&y[j * 4];
    }
}

extern "C" void kernel_launch(void* const* d_in, const int* in_sizes, int n_in,
                              void* d_out, int out_size) {
    const float* emb   = (const float*)d_in[0];
    const float* W_enc = (const float*)d_in[3];
    const float* b_enc = (const float*)d_in[4];
    const float* gamma = (const float*)d_in[5];
    const float* beta  = (const float*)d_in[6];
    float* out = (float*)d_out;

    cudaFuncSetAttribute(gemm_ln_mma,
                         cudaFuncAttributeMaxDynamicSharedMemorySize, SMEM_TOTAL);

    prep_w<<<128, 256>>>(W_enc);

    const int M = in_sizes[0] / DROW;       // 16384
    gemm_ln_mma<<<M / BM, THREADS, SMEM_TOTAL>>>(emb, b_enc, gamma, beta, out);
}